// round 7
// baseline (speedup 1.0000x reference)
#include <cuda_runtime.h>

#define BB 4
#define CC 256
#define HH 56
#define NN 3136
#define NHD 8
#define HD 32
#define NK 784
#define PEW 111
#define BPAD 832   // padded bias row (cols >=784 are -1e30)

__device__ __forceinline__ unsigned tf32c(float f) {
    unsigned u; asm("cvt.rna.tf32.f32 %0, %1;" : "=r"(u) : "f"(f)); return u;
}
__device__ __forceinline__ void mma8(float c[4], const unsigned a[4], unsigned b0, unsigned b1) {
    asm("mma.sync.aligned.m16n8k8.row.col.f32.tf32.tf32.f32 "
        "{%0,%1,%2,%3},{%4,%5,%6,%7},{%8,%9},{%0,%1,%2,%3};"
        : "+f"(c[0]), "+f"(c[1]), "+f"(c[2]), "+f"(c[3])
        : "r"(a[0]), "r"(a[1]), "r"(a[2]), "r"(a[3]), "r"(b0), "r"(b1));
}

// ---------------- scratch ----------------
__device__ float    g_q  [BB*NHD*NN*HD];   // (b, head, n, d)
__device__ float    g_k  [BB*NHD*NK*HD];   // (b, head, m, d)
__device__ float    g_v  [BB*NHD*NK*HD];
__device__ float    g_xkv[BB*NK*CC];       // (b, m, c)
__device__ float    g_ao [BB*NN*CC];       // (b, n, head*32+d)
__device__ unsigned g_wt [1024*CC];        // conv weight transposed tf32
__device__ float    g_bias[NN*BPAD];       // bias table with -1e30 tail

// ---------------- prep ----------------
__global__ void wt_kernel(const float* __restrict__ sr_w) {
    g_wt[blockIdx.x*CC + threadIdx.x] = tf32c(sr_w[threadIdx.x*1024 + blockIdx.x]);
}
__global__ void bias_kernel(const float* __restrict__ pos) {
    int n = blockIdx.x;
    int qi = n/HH, qj = n - qi*HH;
    for (int m = threadIdx.x; m < BPAD; m += 256) {
        float v = -1e30f;
        if (m < NK) {
            int ki = m/HH, kj = m - ki*HH;
            v = pos[(ki-qi+55)*PEW + (kj-qj+55)];
        }
        g_bias[n*BPAD + m] = v;
    }
}

// ---- shared mma core: block 128(M)x64(N), ktile 16; As[16][132], Bs[16][68] ----
__device__ __forceinline__ void mma_ktile(const unsigned* As, const unsigned* Bs,
                                          int wm, int wn, int lane, float acc[2][4][4]) {
    int gr = lane >> 2, gc = lane & 3;
#pragma unroll
    for (int ks = 0; ks < 2; ks++) {
        unsigned a[2][4];
        const unsigned* ak0 = As + (ks*8 + gc)*132 + wm*32;
        const unsigned* ak4 = ak0 + 4*132;
#pragma unroll
        for (int mi = 0; mi < 2; mi++) {
            int r = mi*16 + gr;
            a[mi][0] = ak0[r]; a[mi][1] = ak0[r+8];
            a[mi][2] = ak4[r]; a[mi][3] = ak4[r+8];
        }
        const unsigned* bk0 = Bs + (ks*8 + gc)*68 + wn*32 + gr;
        const unsigned* bk4 = bk0 + 4*68;
#pragma unroll
        for (int nj = 0; nj < 4; nj++) {
            unsigned b0 = bk0[nj*8], b1 = bk4[nj*8];
            mma8(acc[0][nj], a[0], b0, b1);
            mma8(acc[1][nj], a[1], b0, b1);
        }
    }
}

#define GEMM_PRE                                                         \
    __shared__ unsigned As[16*132];                                      \
    __shared__ unsigned Bs[16*68];                                       \
    int tid = threadIdx.x, lane = tid & 31, w = tid >> 5;                \
    int wm = w >> 1, wn = w & 1;                                         \
    int gr = lane >> 2, tg = lane & 3;                                   \
    float acc[2][4][4];                                                  \
    _Pragma("unroll") for (int zi = 0; zi < 2; zi++)                     \
    _Pragma("unroll") for (int zj = 0; zj < 4; zj++)                     \
    _Pragma("unroll") for (int zk = 0; zk < 4; zk++) acc[zi][zj][zk] = 0.f;

// ---------------- 1: Q projection ----------------
__global__ __launch_bounds__(256) void gemm_q_kernel(const float* __restrict__ x,
                                                     const float* __restrict__ Wq) {
    GEMM_PRE
    int b = blockIdx.z, n0 = blockIdx.x*128, c0 = blockIdx.y*64;
    int kk = tid >> 4, m8 = (tid & 15)*8, c4 = (tid & 15)*4;
    bool fok = (n0 + m8) < NN;
    const float* xb = x + b*CC*NN;
    for (int kt = 0; kt < 16; kt++) {
        int k0 = kt*16;
        __syncthreads();
        {
            float4 v0 = make_float4(0,0,0,0), v1 = v0;
            if (fok) { const float* s = xb + (k0+kk)*NN + n0 + m8;
                       v0 = *(const float4*)s; v1 = *(const float4*)(s+4); }
            unsigned* d = As + kk*132 + m8;
            d[0]=tf32c(v0.x); d[1]=tf32c(v0.y); d[2]=tf32c(v0.z); d[3]=tf32c(v0.w);
            d[4]=tf32c(v1.x); d[5]=tf32c(v1.y); d[6]=tf32c(v1.z); d[7]=tf32c(v1.w);
            float4 wv = *(const float4*)(Wq + (k0+kk)*CC + c0 + c4);
            unsigned* e = Bs + kk*68 + c4;
            e[0]=tf32c(wv.x); e[1]=tf32c(wv.y); e[2]=tf32c(wv.z); e[3]=tf32c(wv.w);
        }
        __syncthreads();
        mma_ktile(As, Bs, wm, wn, lane, acc);
    }
#pragma unroll
    for (int nj = 0; nj < 4; nj++) {
        int c = c0 + wn*32 + nj*8 + 2*tg;
        int head = c >> 5, d = c & 31;
        float* qb = g_q + (b*NHD + head)*NN*HD + d;
#pragma unroll
        for (int mi = 0; mi < 2; mi++) {
            int n1 = n0 + wm*32 + mi*16 + gr;
            if (n1 < NN)   *(float2*)(qb + n1*HD)     = make_float2(acc[mi][nj][0], acc[mi][nj][1]);
            if (n1+8 < NN) *(float2*)(qb + (n1+8)*HD) = make_float2(acc[mi][nj][2], acc[mi][nj][3]);
        }
    }
}

// ---------------- 2: SR conv as GEMM (K=1024) ----------------
__global__ __launch_bounds__(256) void gemm_conv_kernel(const float* __restrict__ x,
                                                        const float* __restrict__ sr_b) {
    GEMM_PRE
    int b = blockIdx.z, m0 = blockIdx.x*128, o0 = blockIdx.y*64;
    int kk = tid >> 4, m8 = (tid & 15)*8, c4 = (tid & 15)*4;
    bool fok = (m0 + m8) < NK;
    const float* xb = x + b*CC*NN;
    int sb[8];
#pragma unroll
    for (int c = 0; c < 8; c++) {
        int m = fok ? (m0 + m8 + c) : 0;
        int r = m / 28;
        sb[c] = (2*r)*HH + 2*(m - r*28);
    }
    for (int kt = 0; kt < 64; kt++) {
        int k0 = kt*16;
        __syncthreads();
        {
            int kg = k0 + kk;
            int ic = kg >> 2, kh = (kg >> 1) & 1, kw = kg & 1;
            const float* s = xb + ic*NN + kh*HH + kw;
            unsigned* d = As + kk*132 + m8;
#pragma unroll
            for (int c = 0; c < 8; c++) d[c] = tf32c(fok ? s[sb[c]] : 0.f);
            *(uint4*)(Bs + kk*68 + c4) = *(const uint4*)(g_wt + (k0+kk)*CC + o0 + c4);
        }
        __syncthreads();
        mma_ktile(As, Bs, wm, wn, lane, acc);
    }
#pragma unroll
    for (int nj = 0; nj < 4; nj++) {
        int c = o0 + wn*32 + nj*8 + 2*tg;
        float2 bias = *(const float2*)(sr_b + c);
#pragma unroll
        for (int mi = 0; mi < 2; mi++) {
            int m1 = m0 + wm*32 + mi*16 + gr;
            if (m1 < NK)   *(float2*)(&g_xkv[(b*NK+m1)*CC + c]) =
                make_float2(acc[mi][nj][0]+bias.x, acc[mi][nj][1]+bias.y);
            if (m1+8 < NK) *(float2*)(&g_xkv[(b*NK+m1+8)*CC + c]) =
                make_float2(acc[mi][nj][2]+bias.x, acc[mi][nj][3]+bias.y);
        }
    }
}

// ---------------- 3: LayerNorm ----------------
__global__ void ln_kernel(const float* __restrict__ gamma, const float* __restrict__ beta) {
    int row = blockIdx.x, t = threadIdx.x;
    float v = g_xkv[row*CC + t];
    float s = v, q = v*v;
#pragma unroll
    for (int m = 16; m >= 1; m >>= 1) {
        s += __shfl_xor_sync(0xffffffffu, s, m);
        q += __shfl_xor_sync(0xffffffffu, q, m);
    }
    __shared__ float r1[8], r2[8];
    if ((t & 31) == 0) { r1[t>>5] = s; r2[t>>5] = q; }
    __syncthreads();
    float tot = 0.f, tq = 0.f;
#pragma unroll
    for (int wv = 0; wv < 8; wv++) { tot += r1[wv]; tq += r2[wv]; }
    float mean = tot * (1.f/256.f);
    float var  = tq * (1.f/256.f) - mean*mean;
    float inv  = rsqrtf(var + 1e-5f);
    g_xkv[row*CC + t] = (v - mean)*inv*gamma[t] + beta[t];
}

// ---------------- 4: KV projection (N=512, scatter) ----------------
__global__ __launch_bounds__(256) void gemm_kv_kernel(const float* __restrict__ Wkv) {
    GEMM_PRE
    int b = blockIdx.z, m0 = blockIdx.x*128, c0 = blockIdx.y*64;
    int kk = tid >> 4, c4 = (tid & 15)*4;
    int am = tid >> 1, akc = (tid & 1)*8;
    int arow = m0 + am; if (arow > NK-1) arow = NK-1;
    const float* ap = g_xkv + (b*NK + arow)*CC;
    for (int kt = 0; kt < 16; kt++) {
        int k0 = kt*16;
        __syncthreads();
        {
            float4 v0 = *(const float4*)(ap + k0 + akc);
            float4 v1 = *(const float4*)(ap + k0 + akc + 4);
            As[(akc+0)*132+am]=tf32c(v0.x); As[(akc+1)*132+am]=tf32c(v0.y);
            As[(akc+2)*132+am]=tf32c(v0.z); As[(akc+3)*132+am]=tf32c(v0.w);
            As[(akc+4)*132+am]=tf32c(v1.x); As[(akc+5)*132+am]=tf32c(v1.y);
            As[(akc+6)*132+am]=tf32c(v1.z); As[(akc+7)*132+am]=tf32c(v1.w);
            float4 wv = *(const float4*)(Wkv + (k0+kk)*512 + c0 + c4);
            unsigned* e = Bs + kk*68 + c4;
            e[0]=tf32c(wv.x); e[1]=tf32c(wv.y); e[2]=tf32c(wv.z); e[3]=tf32c(wv.w);
        }
        __syncthreads();
        mma_ktile(As, Bs, wm, wn, lane, acc);
    }
#pragma unroll
    for (int nj = 0; nj < 4; nj++) {
        int c = c0 + wn*32 + nj*8 + 2*tg;
        int d = c >> 4, head = (c >> 1) & 7;
        float* kb = g_k + (b*NHD + head)*NK*HD + d;
        float* vb = g_v + (b*NHD + head)*NK*HD + d;
#pragma unroll
        for (int mi = 0; mi < 2; mi++) {
            int m1 = m0 + wm*32 + mi*16 + gr;
            if (m1 < NK)   { kb[m1*HD]     = acc[mi][nj][0]; vb[m1*HD]     = acc[mi][nj][1]; }
            if (m1+8 < NK) { kb[(m1+8)*HD] = acc[mi][nj][2]; vb[(m1+8)*HD] = acc[mi][nj][3]; }
        }
    }
}

// ---------------- 5: fused flash attention, tf32 mma (Br=128, Bc=64) ------
__global__ __launch_bounds__(256, 2) void attn_kernel() {
    extern __shared__ unsigned smu[];
    unsigned* qs = smu;          // [32][132]
    unsigned* ks = smu + 4224;   // [32][68]
    unsigned* vs = smu + 6400;   // [64][36]
    unsigned* ps = smu + 8704;   // 8 warps x [16][68]
    int b = blockIdx.z, head = blockIdx.y, n0 = blockIdx.x*128;
    int tid = threadIdx.x, lane = tid & 31, w = tid >> 5;
    int gr = lane >> 2, tg = lane & 3;
    const float scale = 0.17677669529663687f;
    int bh = b*NHD + head;
    const float* qg = g_q + bh*NN*HD;
    const float* kg = g_k + bh*NK*HD;
    const float* vg = g_v + bh*NK*HD;

    {   // qs fill: [d][row], scaled + tf32
        int r = tid >> 1, dc = (tid & 1)*16;
        int n = n0 + r; if (n > NN-1) n = NN-1;
        const float* p = qg + n*HD + dc;
#pragma unroll
        for (int c4 = 0; c4 < 4; c4++) {
            float4 v = *(const float4*)(p + c4*4);
            qs[(dc+c4*4+0)*132 + r] = tf32c(v.x*scale);
            qs[(dc+c4*4+1)*132 + r] = tf32c(v.y*scale);
            qs[(dc+c4*4+2)*132 + r] = tf32c(v.z*scale);
            qs[(dc+c4*4+3)*132 + r] = tf32c(v.w*scale);
        }
    }

    int rown0 = n0 + w*16 + gr, rown1 = rown0 + 8;
    int nq0 = rown0 > NN-1 ? NN-1 : rown0;
    int nq1 = rown1 > NN-1 ? NN-1 : rown1;
    const float* brow0 = g_bias + nq0*BPAD;
    const float* brow1 = g_bias + nq1*BPAD;

    float m_i[2] = {-1e30f, -1e30f}, l_i[2] = {0.f, 0.f};
    float co[4][4];
#pragma unroll
    for (int i = 0; i < 4; i++) { co[i][0]=0.f; co[i][1]=0.f; co[i][2]=0.f; co[i][3]=0.f; }
    unsigned* psw = ps + w*16*68;

    for (int t = 0; t < 13; t++) {
        int mb = t*64;
        __syncthreads();
        {   // ks [d][key] + vs [key][d] fill (zero out-of-range keys)
            int kr = tid >> 2, dc = (tid & 3)*8;
            bool ok = (mb + kr) < NK;
            int mr = ok ? (mb + kr) : 0;
            const float* kp = kg + mr*HD + dc;
            float4 a0 = *(const float4*)kp, a1 = *(const float4*)(kp+4);
            if (!ok) { a0 = make_float4(0,0,0,0); a1 = a0; }
            ks[(dc+0)*68+kr]=tf32c(a0.x); ks[(dc+1)*68+kr]=tf32c(a0.y);
            ks[(dc+2)*68+kr]=tf32c(a0.z); ks[(dc+3)*68+kr]=tf32c(a0.w);
            ks[(dc+4)*68+kr]=tf32c(a1.x); ks[(dc+5)*68+kr]=tf32c(a1.y);
            ks[(dc+6)*68+kr]=tf32c(a1.z); ks[(dc+7)*68+kr]=tf32c(a1.w);
            const float* vp = vg + mr*HD + dc;
            float4 w0 = *(const float4*)vp, w1 = *(const float4*)(vp+4);
            if (!ok) { w0 = make_float4(0,0,0,0); w1 = w0; }
            uint4 u0 = make_uint4(tf32c(w0.x), tf32c(w0.y), tf32c(w0.z), tf32c(w0.w));
            uint4 u1 = make_uint4(tf32c(w1.x), tf32c(w1.y), tf32c(w1.z), tf32c(w1.w));
            *(uint4*)(vs + kr*36 + dc)     = u0;
            *(uint4*)(vs + kr*36 + dc + 4) = u1;
        }
        __syncthreads();

        // ---- QK^T: S = 16x64 per warp ----
        float cs[8][4];
#pragma unroll
        for (int i = 0; i < 8; i++) { cs[i][0]=0.f; cs[i][1]=0.f; cs[i][2]=0.f; cs[i][3]=0.f; }
#pragma unroll
        for (int ks8 = 0; ks8 < 4; ks8++) {
            unsigned a[4];
            const unsigned* ak0 = qs + (ks8*8 + tg)*132 + w*16;
            const unsigned* ak4 = ak0 + 4*132;
            a[0] = ak0[gr]; a[1] = ak0[gr+8]; a[2] = ak4[gr]; a[3] = ak4[gr+8];
            const unsigned* bk0 = ks + (ks8*8 + tg)*68 + gr;
            const unsigned* bk4 = bk0 + 4*68;
#pragma unroll
            for (int nj = 0; nj < 8; nj++)
                mma8(cs[nj], a, bk0[nj*8], bk4[nj*8]);
        }

        // ---- bias from precomputed table (includes -1e30 tail mask) ----
#pragma unroll
        for (int nj = 0; nj < 8; nj++) {
            int off = mb + nj*8 + 2*tg;
            float2 b0 = *(const float2*)(brow0 + off);
            float2 b1 = *(const float2*)(brow1 + off);
            cs[nj][0] += b0.x; cs[nj][1] += b0.y;
            cs[nj][2] += b1.x; cs[nj][3] += b1.y;
        }

        // ---- online softmax (rows gr, gr+8; quad reduction) ----
#pragma unroll
        for (int h = 0; h < 2; h++) {
            float tm = -1e30f;
#pragma unroll
            for (int nj = 0; nj < 8; nj++) tm = fmaxf(tm, fmaxf(cs[nj][2*h], cs[nj][2*h+1]));
            tm = fmaxf(tm, __shfl_xor_sync(0xffffffffu, tm, 1));
            tm = fmaxf(tm, __shfl_xor_sync(0xffffffffu, tm, 2));
            float mnew = fmaxf(m_i[h], tm);
            float f = __expf(m_i[h] - mnew);
            m_i[h] = mnew;
            float sum = 0.f;
            unsigned* prow = psw + (gr + 8*h)*68 + 2*tg;
#pragma unroll
            for (int nj = 0; nj < 8; nj++) {
                float p0 = __expf(cs[nj][2*h]   - mnew);
                float p1 = __expf(cs[nj][2*h+1] - mnew);
                sum += p0 + p1;
                *(uint2*)(prow + nj*8) = make_uint2(tf32c(p0), tf32c(p1));
            }
            sum += __shfl_xor_sync(0xffffffffu, sum, 1);
            sum += __shfl_xor_sync(0xffffffffu, sum, 2);
            l_i[h] = l_i[h]*f + sum;
#pragma unroll
            for (int nj = 0; nj < 4; nj++) { co[nj][2*h] *= f; co[nj][2*h+1] *= f; }
        }
        __syncwarp();

        // ---- O += P @ V ----
#pragma unroll
        for (int kk8 = 0; kk8 < 8; kk8++) {
            unsigned a[4];
            const unsigned* p0 = psw + gr*68 + kk8*8 + tg;
            const unsigned* p1 = psw + (gr+8)*68 + kk8*8 + tg;
            a[0] = p0[0]; a[1] = p1[0]; a[2] = p0[4]; a[3] = p1[4];
            const unsigned* b0p = vs + (kk8*8 + tg)*36 + gr;
            const unsigned* b1p = b0p + 4*36;
#pragma unroll
            for (int nj = 0; nj < 4; nj++)
                mma8(co[nj], a, b0p[nj*8], b1p[nj*8]);
        }
        __syncwarp();
    }

    float inv0 = 1.f/l_i[0], inv1 = 1.f/l_i[1];
#pragma unroll
    for (int nj = 0; nj < 4; nj++) {
        int d = nj*8 + 2*tg;
        if (rown0 < NN)
            *(float2*)&g_ao[(b*NN + rown0)*CC + head*HD + d] =
                make_float2(co[nj][0]*inv0, co[nj][1]*inv0);
        if (rown1 < NN)
            *(float2*)&g_ao[(b*NN + rown1)*CC + head*HD + d] =
                make_float2(co[nj][2]*inv1, co[nj][3]*inv1);
    }
}

// ---------------- 6: output projection + NCHW transpose ----------------
__global__ __launch_bounds__(256) void gemm_proj_kernel(const float* __restrict__ pw,
                                                        const float* __restrict__ pb,
                                                        float* __restrict__ out) {
    GEMM_PRE
    int b = blockIdx.z, n0 = blockIdx.x*128, c0 = blockIdx.y*64;
    int kk = tid >> 4, c4 = (tid & 15)*4;
    int am = tid >> 1, akc = (tid & 1)*8;
    int arow = n0 + am; if (arow > NN-1) arow = NN-1;
    const float* ap = g_ao + (b*NN + arow)*CC;
    for (int kt = 0; kt < 16; kt++) {
        int k0 = kt*16;
        __syncthreads();
        {
            float4 v0 = *(const float4*)(ap + k0 + akc);
            float4 v1 = *(const float4*)(ap + k0 + akc + 4);
            As[(akc+0)*132+am]=tf32c(v0.x); As[(akc+1)*132+am]=tf32c(v0.y);
            As[(akc+2)*132+am]=tf32c(v0.z); As[(akc+3)*132+am]=tf32c(v0.w);
            As[(akc+4)*132+am]=tf32c(v1.x); As[(akc+5)*132+am]=tf32c(v1.y);
            As[(akc+6)*132+am]=tf32c(v1.z); As[(akc+7)*132+am]=tf32c(v1.w);
            float4 wv = *(const float4*)(pw + (k0+kk)*CC + c0 + c4);
            unsigned* e = Bs + kk*68 + c4;
            e[0]=tf32c(wv.x); e[1]=tf32c(wv.y); e[2]=tf32c(wv.z); e[3]=tf32c(wv.w);
        }
        __syncthreads();
        mma_ktile(As, Bs, wm, wn, lane, acc);
    }
#pragma unroll
    for (int nj = 0; nj < 4; nj++) {
        int c = c0 + wn*32 + nj*8 + 2*tg;
        float2 pbv = *(const float2*)(pb + c);
        float* o0 = out + (b*CC + c)*NN;
        float* o1 = o0 + NN;
#pragma unroll
        for (int mi = 0; mi < 2; mi++) {
            int n1 = n0 + wm*32 + mi*16 + gr;
            if (n1 < NN)   { o0[n1]   = acc[mi][nj][0] + pbv.x; o1[n1]   = acc[mi][nj][1] + pbv.y; }
            if (n1+8 < NN) { o0[n1+8] = acc[mi][nj][2] + pbv.x; o1[n1+8] = acc[mi][nj][3] + pbv.y; }
        }
    }
}

// ---------------- launch ----------------
extern "C" void kernel_launch(void* const* d_in, const int* in_sizes, int n_in,
                              void* d_out, int out_size) {
    const float* x    = (const float*)d_in[0];
    const float* Wq   = (const float*)d_in[1];
    const float* Wkv  = (const float*)d_in[2];
    const float* sr_w = (const float*)d_in[3];
    const float* sr_b = (const float*)d_in[4];
    const float* ln_g = (const float*)d_in[5];
    const float* ln_b = (const float*)d_in[6];
    const float* pos  = (const float*)d_in[7];
    const float* pw   = (const float*)d_in[8];
    const float* pb   = (const float*)d_in[9];
    float* out = (float*)d_out;

    static int smem_set = 0;
    if (!smem_set) {
        cudaFuncSetAttribute(attn_kernel, cudaFuncAttributeMaxDynamicSharedMemorySize, 69632);
        smem_set = 1;
    }

    wt_kernel       <<<1024, 256>>>(sr_w);
    bias_kernel     <<<NN, 256>>>(pos);
    gemm_q_kernel   <<<dim3(25, 4, BB), 256>>>(x, Wq);
    gemm_conv_kernel<<<dim3(7, 4, BB), 256>>>(x, sr_b);
    ln_kernel       <<<BB*NK, 256>>>(ln_g, ln_b);
    gemm_kv_kernel  <<<dim3(7, 8, BB), 256>>>(Wkv);
    attn_kernel     <<<dim3(25, 8, BB), 256, 69632>>>();
    gemm_proj_kernel<<<dim3(25, 4, BB), 256>>>(pb ? pw : pw, pb, out);
}

// round 8
// speedup vs baseline: 1.1459x; 1.1459x over previous
#include <cuda_runtime.h>

#define BB 4
#define CC 256
#define HH 56
#define NN 3136
#define NHD 8
#define HD 32
#define NK 784
#define PEW 111

__device__ __forceinline__ unsigned tf32c(float f) {
    unsigned u; asm("cvt.rna.tf32.f32 %0, %1;" : "=r"(u) : "f"(f)); return u;
}
__device__ __forceinline__ void mma8(float c[4], const unsigned a[4], unsigned b0, unsigned b1) {
    asm("mma.sync.aligned.m16n8k8.row.col.f32.tf32.tf32.f32 "
        "{%0,%1,%2,%3},{%4,%5,%6,%7},{%8,%9},{%0,%1,%2,%3};"
        : "+f"(c[0]), "+f"(c[1]), "+f"(c[2]), "+f"(c[3])
        : "r"(a[0]), "r"(a[1]), "r"(a[2]), "r"(a[3]), "r"(b0), "r"(b1));
}

// ---------------- scratch ----------------
__device__ float    g_q   [BB*NHD*NN*HD];   // (b, head, n, d)
__device__ float    g_k   [BB*NHD*NK*HD];   // (b, head, m, d)
__device__ float    g_v   [BB*NHD*NK*HD];
__device__ float    g_xkvp[4*BB*NK*CC];     // conv partial sums (K-split)
__device__ float    g_xkv [BB*NK*CC];       // LN output
__device__ float    g_ao  [BB*NN*CC];       // (b, n, head*32+d)
__device__ unsigned g_wt  [1024*CC];        // conv weight transposed tf32

// ---------------- prep ----------------
__global__ void wt_kernel(const float* __restrict__ sr_w) {
    g_wt[blockIdx.x*CC + threadIdx.x] = tf32c(sr_w[threadIdx.x*1024 + blockIdx.x]);
}

// ---- shared mma core: block 128(M)x64(N), ktile 16; As[16][132], Bs[16][68] ----
__device__ __forceinline__ void mma_ktile(const unsigned* As, const unsigned* Bs,
                                          int wm, int wn, int lane, float acc[2][4][4]) {
    int gr = lane >> 2, gc = lane & 3;
#pragma unroll
    for (int ks = 0; ks < 2; ks++) {
        unsigned a[2][4];
        const unsigned* ak0 = As + (ks*8 + gc)*132 + wm*32;
        const unsigned* ak4 = ak0 + 4*132;
#pragma unroll
        for (int mi = 0; mi < 2; mi++) {
            int r = mi*16 + gr;
            a[mi][0] = ak0[r]; a[mi][1] = ak0[r+8];
            a[mi][2] = ak4[r]; a[mi][3] = ak4[r+8];
        }
        const unsigned* bk0 = Bs + (ks*8 + gc)*68 + wn*32 + gr;
        const unsigned* bk4 = bk0 + 4*68;
#pragma unroll
        for (int nj = 0; nj < 4; nj++) {
            unsigned b0 = bk0[nj*8], b1 = bk4[nj*8];
            mma8(acc[0][nj], a[0], b0, b1);
            mma8(acc[1][nj], a[1], b0, b1);
        }
    }
}

#define GEMM_PRE                                                         \
    __shared__ unsigned As[16*132];                                      \
    __shared__ unsigned Bs[16*68];                                       \
    int tid = threadIdx.x, lane = tid & 31, w = tid >> 5;                \
    int wm = w >> 1, wn = w & 1;                                         \
    int gr = lane >> 2, tg = lane & 3;                                   \
    float acc[2][4][4];                                                  \
    _Pragma("unroll") for (int zi = 0; zi < 2; zi++)                     \
    _Pragma("unroll") for (int zj = 0; zj < 4; zj++)                     \
    _Pragma("unroll") for (int zk = 0; zk < 4; zk++) acc[zi][zj][zk] = 0.f;

// ---------------- 1: Q projection ----------------
__global__ __launch_bounds__(256) void gemm_q_kernel(const float* __restrict__ x,
                                                     const float* __restrict__ Wq) {
    GEMM_PRE
    int b = blockIdx.z, n0 = blockIdx.x*128, c0 = blockIdx.y*64;
    int kk = tid >> 4, m8 = (tid & 15)*8, c4 = (tid & 15)*4;
    bool fok = (n0 + m8) < NN;
    const float* xb = x + b*CC*NN;
    for (int kt = 0; kt < 16; kt++) {
        int k0 = kt*16;
        __syncthreads();
        {
            float4 v0 = make_float4(0,0,0,0), v1 = v0;
            if (fok) { const float* s = xb + (k0+kk)*NN + n0 + m8;
                       v0 = *(const float4*)s; v1 = *(const float4*)(s+4); }
            unsigned* d = As + kk*132 + m8;
            d[0]=tf32c(v0.x); d[1]=tf32c(v0.y); d[2]=tf32c(v0.z); d[3]=tf32c(v0.w);
            d[4]=tf32c(v1.x); d[5]=tf32c(v1.y); d[6]=tf32c(v1.z); d[7]=tf32c(v1.w);
            float4 wv = *(const float4*)(Wq + (k0+kk)*CC + c0 + c4);
            unsigned* e = Bs + kk*68 + c4;
            e[0]=tf32c(wv.x); e[1]=tf32c(wv.y); e[2]=tf32c(wv.z); e[3]=tf32c(wv.w);
        }
        __syncthreads();
        mma_ktile(As, Bs, wm, wn, lane, acc);
    }
#pragma unroll
    for (int nj = 0; nj < 4; nj++) {
        int c = c0 + wn*32 + nj*8 + 2*tg;
        int head = c >> 5, d = c & 31;
        float* qb = g_q + (b*NHD + head)*NN*HD + d;
#pragma unroll
        for (int mi = 0; mi < 2; mi++) {
            int n1 = n0 + wm*32 + mi*16 + gr;
            if (n1 < NN)   *(float2*)(qb + n1*HD)     = make_float2(acc[mi][nj][0], acc[mi][nj][1]);
            if (n1+8 < NN) *(float2*)(qb + (n1+8)*HD) = make_float2(acc[mi][nj][2], acc[mi][nj][3]);
        }
    }
}

// ---------------- 2: SR conv as GEMM, K-split x4 (K=256 each) ----------------
__global__ __launch_bounds__(256) void gemm_conv_kernel(const float* __restrict__ x) {
    GEMM_PRE
    int b = blockIdx.z;
    int part = blockIdx.y >> 2;
    int o0 = (blockIdx.y & 3) * 64;
    int m0 = blockIdx.x * 128;
    int kk = tid >> 4, m8 = (tid & 15)*8, c4 = (tid & 15)*4;
    bool fok = (m0 + m8) < NK;
    const float* xb = x + b*CC*NN;
    int sb[8];
#pragma unroll
    for (int c = 0; c < 8; c++) {
        int m = fok ? (m0 + m8 + c) : 0;
        int r = m / 28;
        sb[c] = (2*r)*HH + 2*(m - r*28);
    }
    int kbase = part*256;

    float va[8]; uint4 vb4;
    {   // prefetch tile 0
        int kg = kbase + kk;
        int ic = kg >> 2, kh = (kg >> 1) & 1, kw = kg & 1;
        const float* s = xb + ic*NN + kh*HH + kw;
#pragma unroll
        for (int c = 0; c < 8; c++) va[c] = fok ? s[sb[c]] : 0.f;
        vb4 = *(const uint4*)(g_wt + (kbase+kk)*CC + o0 + c4);
    }
    for (int kt = 0; kt < 16; kt++) {
        unsigned* d = As + kk*132 + m8;
#pragma unroll
        for (int c = 0; c < 8; c++) d[c] = tf32c(va[c]);
        *(uint4*)(Bs + kk*68 + c4) = vb4;
        __syncthreads();
        if (kt < 15) {  // prefetch next tile (overlaps mma)
            int kg = kbase + (kt+1)*16 + kk;
            int ic = kg >> 2, kh = (kg >> 1) & 1, kw = kg & 1;
            const float* s = xb + ic*NN + kh*HH + kw;
#pragma unroll
            for (int c = 0; c < 8; c++) va[c] = fok ? s[sb[c]] : 0.f;
            vb4 = *(const uint4*)(g_wt + (kg - kk + kk)*CC + o0 + c4);
        }
        mma_ktile(As, Bs, wm, wn, lane, acc);
        __syncthreads();
    }
    float* dstp = g_xkvp + part*(BB*NK*CC) + (b*NK)*CC;
#pragma unroll
    for (int nj = 0; nj < 4; nj++) {
        int c = o0 + wn*32 + nj*8 + 2*tg;
#pragma unroll
        for (int mi = 0; mi < 2; mi++) {
            int m1 = m0 + wm*32 + mi*16 + gr;
            if (m1 < NK)   *(float2*)(&dstp[m1*CC + c]) =
                make_float2(acc[mi][nj][0], acc[mi][nj][1]);
            if (m1+8 < NK) *(float2*)(&dstp[(m1+8)*CC + c]) =
                make_float2(acc[mi][nj][2], acc[mi][nj][3]);
        }
    }
}

// ---------------- 3: LayerNorm (sums 4 conv partials + bias) ----------------
__global__ void ln_kernel(const float* __restrict__ gamma, const float* __restrict__ beta,
                          const float* __restrict__ sr_b) {
    int row = blockIdx.x, t = threadIdx.x;
    int idx = row*CC + t;
    const int stride = BB*NK*CC;
    float v = ((g_xkvp[idx] + g_xkvp[idx + stride]) +
               (g_xkvp[idx + 2*stride] + g_xkvp[idx + 3*stride])) + sr_b[t];
    float s = v, q = v*v;
#pragma unroll
    for (int m = 16; m >= 1; m >>= 1) {
        s += __shfl_xor_sync(0xffffffffu, s, m);
        q += __shfl_xor_sync(0xffffffffu, q, m);
    }
    __shared__ float r1[8], r2[8];
    if ((t & 31) == 0) { r1[t>>5] = s; r2[t>>5] = q; }
    __syncthreads();
    float tot = 0.f, tq = 0.f;
#pragma unroll
    for (int wv = 0; wv < 8; wv++) { tot += r1[wv]; tq += r2[wv]; }
    float mean = tot * (1.f/256.f);
    float var  = tq * (1.f/256.f) - mean*mean;
    float inv  = rsqrtf(var + 1e-5f);
    g_xkv[row*CC + t] = (v - mean)*inv*gamma[t] + beta[t];
}

// ---------------- 4: KV projection (N=512, scatter) ----------------
__global__ __launch_bounds__(256) void gemm_kv_kernel(const float* __restrict__ Wkv) {
    GEMM_PRE
    int b = blockIdx.z, m0 = blockIdx.x*128, c0 = blockIdx.y*64;
    int kk = tid >> 4, c4 = (tid & 15)*4;
    int am = tid >> 1, akc = (tid & 1)*8;
    int arow = m0 + am; if (arow > NK-1) arow = NK-1;
    const float* ap = g_xkv + (b*NK + arow)*CC;
    for (int kt = 0; kt < 16; kt++) {
        int k0 = kt*16;
        __syncthreads();
        {
            float4 v0 = *(const float4*)(ap + k0 + akc);
            float4 v1 = *(const float4*)(ap + k0 + akc + 4);
            As[(akc+0)*132+am]=tf32c(v0.x); As[(akc+1)*132+am]=tf32c(v0.y);
            As[(akc+2)*132+am]=tf32c(v0.z); As[(akc+3)*132+am]=tf32c(v0.w);
            As[(akc+4)*132+am]=tf32c(v1.x); As[(akc+5)*132+am]=tf32c(v1.y);
            As[(akc+6)*132+am]=tf32c(v1.z); As[(akc+7)*132+am]=tf32c(v1.w);
            float4 wv = *(const float4*)(Wkv + (k0+kk)*512 + c0 + c4);
            unsigned* e = Bs + kk*68 + c4;
            e[0]=tf32c(wv.x); e[1]=tf32c(wv.y); e[2]=tf32c(wv.z); e[3]=tf32c(wv.w);
        }
        __syncthreads();
        mma_ktile(As, Bs, wm, wn, lane, acc);
    }
#pragma unroll
    for (int nj = 0; nj < 4; nj++) {
        int c = c0 + wn*32 + nj*8 + 2*tg;
        int d = c >> 4, head = (c >> 1) & 7;
        float* kb = g_k + (b*NHD + head)*NK*HD + d;
        float* vb = g_v + (b*NHD + head)*NK*HD + d;
#pragma unroll
        for (int mi = 0; mi < 2; mi++) {
            int m1 = m0 + wm*32 + mi*16 + gr;
            if (m1 < NK)   { kb[m1*HD]     = acc[mi][nj][0]; vb[m1*HD]     = acc[mi][nj][1]; }
            if (m1+8 < NK) { kb[(m1+8)*HD] = acc[mi][nj][2]; vb[(m1+8)*HD] = acc[mi][nj][3]; }
        }
    }
}

// ---------------- 5: fused flash attention, tf32 mma (Br=128, Bc=64) ------
__global__ __launch_bounds__(256, 2) void attn_kernel(const float* __restrict__ pos_emb) {
    extern __shared__ unsigned smu[];
    unsigned* qs = smu;          // [32][132]
    unsigned* ks = smu + 4224;   // [32][68]
    unsigned* vs = smu + 6400;   // [64][36]
    unsigned* ps = smu + 8704;   // 8 warps x [16][68]
    int b = blockIdx.z, head = blockIdx.y, n0 = blockIdx.x*128;
    int tid = threadIdx.x, lane = tid & 31, w = tid >> 5;
    int gr = lane >> 2, tg = lane & 3;
    const float scale = 0.17677669529663687f;
    int bh = b*NHD + head;
    const float* qg = g_q + bh*NN*HD;
    const float* kg = g_k + bh*NK*HD;
    const float* vg = g_v + bh*NK*HD;

    {   // qs fill: [d][row], scaled + tf32
        int r = tid >> 1, dc = (tid & 1)*16;
        int n = n0 + r; if (n > NN-1) n = NN-1;
        const float* p = qg + n*HD + dc;
#pragma unroll
        for (int c4 = 0; c4 < 4; c4++) {
            float4 v = *(const float4*)(p + c4*4);
            qs[(dc+c4*4+0)*132 + r] = tf32c(v.x*scale);
            qs[(dc+c4*4+1)*132 + r] = tf32c(v.y*scale);
            qs[(dc+c4*4+2)*132 + r] = tf32c(v.z*scale);
            qs[(dc+c4*4+3)*132 + r] = tf32c(v.w*scale);
        }
    }

    int rown0 = n0 + w*16 + gr, rown1 = rown0 + 8;
    int nq0 = rown0 > NN-1 ? NN-1 : rown0;
    int nq1 = rown1 > NN-1 ? NN-1 : rown1;
    int qi0 = nq0/HH, qj0 = nq0 - qi0*HH;
    int qi1 = nq1/HH, qj1 = nq1 - qi1*HH;

    float m_i[2] = {-1e30f, -1e30f}, l_i[2] = {0.f, 0.f};
    float co[4][4];
#pragma unroll
    for (int i = 0; i < 4; i++) { co[i][0]=0.f; co[i][1]=0.f; co[i][2]=0.f; co[i][3]=0.f; }
    unsigned* psw = ps + w*16*68;

    for (int t = 0; t < 13; t++) {
        int mb = t*64;
        __syncthreads();
        {   // ks [d][key] + vs [key][d] fill (zero out-of-range keys)
            int kr = tid >> 2, dc = (tid & 3)*8;
            bool ok = (mb + kr) < NK;
            int mr = ok ? (mb + kr) : 0;
            const float* kp = kg + mr*HD + dc;
            float4 a0 = *(const float4*)kp, a1 = *(const float4*)(kp+4);
            if (!ok) { a0 = make_float4(0,0,0,0); a1 = a0; }
            ks[(dc+0)*68+kr]=tf32c(a0.x); ks[(dc+1)*68+kr]=tf32c(a0.y);
            ks[(dc+2)*68+kr]=tf32c(a0.z); ks[(dc+3)*68+kr]=tf32c(a0.w);
            ks[(dc+4)*68+kr]=tf32c(a1.x); ks[(dc+5)*68+kr]=tf32c(a1.y);
            ks[(dc+6)*68+kr]=tf32c(a1.z); ks[(dc+7)*68+kr]=tf32c(a1.w);
            const float* vp = vg + mr*HD + dc;
            float4 w0 = *(const float4*)vp, w1 = *(const float4*)(vp+4);
            if (!ok) { w0 = make_float4(0,0,0,0); w1 = w0; }
            uint4 u0 = make_uint4(tf32c(w0.x), tf32c(w0.y), tf32c(w0.z), tf32c(w0.w));
            uint4 u1 = make_uint4(tf32c(w1.x), tf32c(w1.y), tf32c(w1.z), tf32c(w1.w));
            *(uint4*)(vs + kr*36 + dc)     = u0;
            *(uint4*)(vs + kr*36 + dc + 4) = u1;
        }
        __syncthreads();

        // ---- QK^T: S = 16x64 per warp ----
        float cs[8][4];
#pragma unroll
        for (int i = 0; i < 8; i++) { cs[i][0]=0.f; cs[i][1]=0.f; cs[i][2]=0.f; cs[i][3]=0.f; }
#pragma unroll
        for (int ks8 = 0; ks8 < 4; ks8++) {
            unsigned a[4];
            const unsigned* ak0 = qs + (ks8*8 + tg)*132 + w*16;
            const unsigned* ak4 = ak0 + 4*132;
            a[0] = ak0[gr]; a[1] = ak0[gr+8]; a[2] = ak4[gr]; a[3] = ak4[gr+8];
            const unsigned* bk0 = ks + (ks8*8 + tg)*68 + gr;
            const unsigned* bk4 = bk0 + 4*68;
#pragma unroll
            for (int nj = 0; nj < 8; nj++)
                mma8(cs[nj], a, bk0[nj*8], bk4[nj*8]);
        }

        // ---- bias + mask (inline from L2-resident pos_emb) ----
#pragma unroll
        for (int nj = 0; nj < 8; nj++) {
            int mk = mb + nj*8 + 2*tg;
            if (mk < NK) {
                int ki = mk/HH, kj = mk - (mk/HH)*HH;
                int ki2 = (kj == HH-1) ? ki+1 : ki;
                int kj2 = (kj == HH-1) ? 0 : kj+1;
                cs[nj][0] += __ldg(&pos_emb[(ki -qi0+55)*PEW + (kj -qj0+55)]);
                cs[nj][1] += __ldg(&pos_emb[(ki2-qi0+55)*PEW + (kj2-qj0+55)]);
                cs[nj][2] += __ldg(&pos_emb[(ki -qi1+55)*PEW + (kj -qj1+55)]);
                cs[nj][3] += __ldg(&pos_emb[(ki2-qi1+55)*PEW + (kj2-qj1+55)]);
            } else {
                cs[nj][0] = -1e30f; cs[nj][1] = -1e30f;
                cs[nj][2] = -1e30f; cs[nj][3] = -1e30f;
            }
        }

        // ---- online softmax (rows gr, gr+8; quad reduction) ----
#pragma unroll
        for (int h = 0; h < 2; h++) {
            float tm = -1e30f;
#pragma unroll
            for (int nj = 0; nj < 8; nj++) tm = fmaxf(tm, fmaxf(cs[nj][2*h], cs[nj][2*h+1]));
            tm = fmaxf(tm, __shfl_xor_sync(0xffffffffu, tm, 1));
            tm = fmaxf(tm, __shfl_xor_sync(0xffffffffu, tm, 2));
            float mnew = fmaxf(m_i[h], tm);
            float f = __expf(m_i[h] - mnew);
            m_i[h] = mnew;
            float sum = 0.f;
            unsigned* prow = psw + (gr + 8*h)*68 + 2*tg;
#pragma unroll
            for (int nj = 0; nj < 8; nj++) {
                float p0 = __expf(cs[nj][2*h]   - mnew);
                float p1 = __expf(cs[nj][2*h+1] - mnew);
                sum += p0 + p1;
                *(uint2*)(prow + nj*8) = make_uint2(tf32c(p0), tf32c(p1));
            }
            sum += __shfl_xor_sync(0xffffffffu, sum, 1);
            sum += __shfl_xor_sync(0xffffffffu, sum, 2);
            l_i[h] = l_i[h]*f + sum;
#pragma unroll
            for (int nj = 0; nj < 4; nj++) { co[nj][2*h] *= f; co[nj][2*h+1] *= f; }
        }
        __syncwarp();

        // ---- O += P @ V ----
#pragma unroll
        for (int kk8 = 0; kk8 < 8; kk8++) {
            unsigned a[4];
            const unsigned* p0 = psw + gr*68 + kk8*8 + tg;
            const unsigned* p1 = psw + (gr+8)*68 + kk8*8 + tg;
            a[0] = p0[0]; a[1] = p1[0]; a[2] = p0[4]; a[3] = p1[4];
            const unsigned* b0p = vs + (kk8*8 + tg)*36 + gr;
            const unsigned* b1p = b0p + 4*36;
#pragma unroll
            for (int nj = 0; nj < 4; nj++)
                mma8(co[nj], a, b0p[nj*8], b1p[nj*8]);
        }
        __syncwarp();
    }

    float inv0 = 1.f/l_i[0], inv1 = 1.f/l_i[1];
#pragma unroll
    for (int nj = 0; nj < 4; nj++) {
        int d = nj*8 + 2*tg;
        if (rown0 < NN)
            *(float2*)&g_ao[(b*NN + rown0)*CC + head*HD + d] =
                make_float2(co[nj][0]*inv0, co[nj][1]*inv0);
        if (rown1 < NN)
            *(float2*)&g_ao[(b*NN + rown1)*CC + head*HD + d] =
                make_float2(co[nj][2]*inv1, co[nj][3]*inv1);
    }
}

// ---------------- 6: output projection + NCHW transpose ----------------
__global__ __launch_bounds__(256) void gemm_proj_kernel(const float* __restrict__ pw,
                                                        const float* __restrict__ pb,
                                                        float* __restrict__ out) {
    GEMM_PRE
    int b = blockIdx.z, n0 = blockIdx.x*128, c0 = blockIdx.y*64;
    int kk = tid >> 4, c4 = (tid & 15)*4;
    int am = tid >> 1, akc = (tid & 1)*8;
    int arow = n0 + am; if (arow > NN-1) arow = NN-1;
    const float* ap = g_ao + (b*NN + arow)*CC;
    for (int kt = 0; kt < 16; kt++) {
        int k0 = kt*16;
        __syncthreads();
        {
            float4 v0 = *(const float4*)(ap + k0 + akc);
            float4 v1 = *(const float4*)(ap + k0 + akc + 4);
            As[(akc+0)*132+am]=tf32c(v0.x); As[(akc+1)*132+am]=tf32c(v0.y);
            As[(akc+2)*132+am]=tf32c(v0.z); As[(akc+3)*132+am]=tf32c(v0.w);
            As[(akc+4)*132+am]=tf32c(v1.x); As[(akc+5)*132+am]=tf32c(v1.y);
            As[(akc+6)*132+am]=tf32c(v1.z); As[(akc+7)*132+am]=tf32c(v1.w);
            float4 wv = *(const float4*)(pw + (k0+kk)*CC + c0 + c4);
            unsigned* e = Bs + kk*68 + c4;
            e[0]=tf32c(wv.x); e[1]=tf32c(wv.y); e[2]=tf32c(wv.z); e[3]=tf32c(wv.w);
        }
        __syncthreads();
        mma_ktile(As, Bs, wm, wn, lane, acc);
    }
#pragma unroll
    for (int nj = 0; nj < 4; nj++) {
        int c = c0 + wn*32 + nj*8 + 2*tg;
        float2 pbv = *(const float2*)(pb + c);
        float* o0 = out + (b*CC + c)*NN;
        float* o1 = o0 + NN;
#pragma unroll
        for (int mi = 0; mi < 2; mi++) {
            int n1 = n0 + wm*32 + mi*16 + gr;
            if (n1 < NN)   { o0[n1]   = acc[mi][nj][0] + pbv.x; o1[n1]   = acc[mi][nj][1] + pbv.y; }
            if (n1+8 < NN) { o0[n1+8] = acc[mi][nj][2] + pbv.x; o1[n1+8] = acc[mi][nj][3] + pbv.y; }
        }
    }
}

// ---------------- launch ----------------
extern "C" void kernel_launch(void* const* d_in, const int* in_sizes, int n_in,
                              void* d_out, int out_size) {
    const float* x    = (const float*)d_in[0];
    const float* Wq   = (const float*)d_in[1];
    const float* Wkv  = (const float*)d_in[2];
    const float* sr_w = (const float*)d_in[3];
    const float* sr_b = (const float*)d_in[4];
    const float* ln_g = (const float*)d_in[5];
    const float* ln_b = (const float*)d_in[6];
    const float* pos  = (const float*)d_in[7];
    const float* pw   = (const float*)d_in[8];
    const float* pb   = (const float*)d_in[9];
    float* out = (float*)d_out;

    static int smem_set = 0;
    if (!smem_set) {
        cudaFuncSetAttribute(attn_kernel, cudaFuncAttributeMaxDynamicSharedMemorySize, 69632);
        smem_set = 1;
    }

    wt_kernel       <<<1024, 256>>>(sr_w);
    gemm_q_kernel   <<<dim3(25, 4, BB), 256>>>(x, Wq);
    gemm_conv_kernel<<<dim3(7, 16, BB), 256>>>(x);
    ln_kernel       <<<BB*NK, 256>>>(ln_g, ln_b, sr_b);
    gemm_kv_kernel  <<<dim3(7, 8, BB), 256>>>(Wkv);
    attn_kernel     <<<dim3(25, 8, BB), 256, 69632>>>(pos);
    gemm_proj_kernel<<<dim3(25, 4, BB), 256>>>(pw, pb, out);
}